// round 13
// baseline (speedup 1.0000x reference)
#include <cuda_runtime.h>
#include <cuda_bf16.h>
#include <stdint.h>

#define NN 1024
#define EE 32
#define RSTRIDE 80                      // bf16 row pitch in bytes (40 bf16)

// Scratch (no allocations allowed)
__device__ float g_part[128];
__device__ unsigned int g_done = 0;

__device__ __forceinline__ void ldsm4(unsigned* r, unsigned addr) {
    asm volatile("ldmatrix.sync.aligned.m8n8.x4.shared.b16 {%0,%1,%2,%3}, [%4];"
        : "=r"(r[0]), "=r"(r[1]), "=r"(r[2]), "=r"(r[3]) : "r"(addr));
}
__device__ __forceinline__ void mma_bf16(float* d, const unsigned* a,
                                         const unsigned* bf, const float* c) {
    asm volatile("mma.sync.aligned.m16n8k16.row.col.f32.bf16.bf16.f32 "
        "{%0,%1,%2,%3}, {%4,%5,%6,%7}, {%8,%9}, {%10,%11,%12,%13};"
        : "=f"(d[0]), "=f"(d[1]), "=f"(d[2]), "=f"(d[3])
        : "r"(a[0]), "r"(a[1]), "r"(a[2]), "r"(a[3]),
          "r"(bf[0]), "r"(bf[1]),
          "f"(c[0]), "f"(c[1]), "f"(c[2]), "f"(c[3]));
}

// ---------------------------------------------------------------------------
// One launch. grid (32 i-tiles, 4 batches) x 512 threads, 1 CTA/SM (~91KB smem).
// Phase A: y -> bf16 smem [1024][40] (80B pitch), norms fp32 from rounded bf16.
// Phase B: Gram via mma.sync bf16; mask LDGs in a depth-4 circular pipeline
// (prefetch distance > DRAM latency); epilogue: 3 MUFU + Taylor-5 e^sim.
// Additive row sums {T,A,P,C}; analytic diag; deterministic 128-leaf tree.
// ---------------------------------------------------------------------------
__global__ void __launch_bounds__(512, 1)
fused_kernel(const float* __restrict__ emb,
             const float* __restrict__ coords,
             const int*   __restrict__ mask,
             float*       __restrict__ out) {
    extern __shared__ char smem[];
    char*   sBc  = smem;                                         // [1024][80B]
    float*  sN   = reinterpret_cast<float*>(smem + NN * RSTRIDE); // [1024]
    float4* sRow = reinterpret_cast<float4*>(sN + NN);           // [32][8]
    __shared__ int sIsLast;

    const int tid  = threadIdx.x;
    const int b    = blockIdx.y;
    const int i0   = blockIdx.x * 32;
    const int warp = tid >> 5;          // 0..15
    const int lane = tid & 31;
    const int g    = lane >> 2;         // 0..7
    const int tg   = lane & 3;          // 0..3
    const int rg   = warp >> 3;         // row-group 0/1
    const int q    = warp & 7;          // column eighth

    // ---------------- Phase A: bf16 y + norms (2 rows/thread) ---------------
#pragma unroll
    for (int k = 0; k < 2; k++) {
        const int j = tid + k * 512;
        const float* ep = emb + ((size_t)(b * NN + j)) * EE;
        float v[EE];
#pragma unroll
        for (int e = 0; e < EE; e += 4) {
            float4 t = *reinterpret_cast<const float4*>(ep + e);
            v[e] = t.x; v[e + 1] = t.y; v[e + 2] = t.z; v[e + 3] = t.w;
        }
        float2 c2 = *reinterpret_cast<const float2*>(coords + ((size_t)(b * NN + j)) * 2);
        v[0] += c2.x; v[1] += c2.y;
        unsigned w[16];
        float n = 0.f;
#pragma unroll
        for (int p = 0; p < 16; p++) {
            __nv_bfloat162 h2 = __floats2bfloat162_rn(v[2 * p], v[2 * p + 1]);
            w[p] = *reinterpret_cast<unsigned*>(&h2);
            float lo = __bfloat162float(__low2bfloat16(h2));
            float hi = __bfloat162float(__high2bfloat16(h2));
            n = fmaf(lo, lo, n);
            n = fmaf(hi, hi, n);
        }
        uint4* row = reinterpret_cast<uint4*>(sBc + (size_t)j * RSTRIDE);
        row[0] = make_uint4(w[0], w[1], w[2], w[3]);
        row[1] = make_uint4(w[4], w[5], w[6], w[7]);
        row[2] = make_uint4(w[8], w[9], w[10], w[11]);
        row[3] = make_uint4(w[12], w[13], w[14], w[15]);
        sN[j] = n;
    }
    __syncthreads();

    // ---------------- Phase B: mma Gram + pipelined mask + epilogue ---------
    const unsigned sB_u32 = (unsigned)__cvta_generic_to_shared(sBc);

    // A fragments (rows i0 + rg*16 .. +15), k-lo and k-hi, held in registers
    unsigned aLo[4], aHi[4];
    {
        const int m = lane >> 3;                    // matrix index 0..3
        const int rowA = i0 + rg * 16 + ((m & 1) << 3) + (lane & 7);
        const unsigned colb = (unsigned)((m >> 1) << 4);
        unsigned addr = sB_u32 + (unsigned)rowA * RSTRIDE + colb;
        ldsm4(aLo, addr);
        ldsm4(aHi, addr + 32);
    }

    const int i_lo = i0 + rg * 16 + g;
    const int i_hi = i_lo + 8;
    const float ni_lo = sN[i_lo];
    const float ni_hi = sN[i_hi];
    const int* pL = mask + ((size_t)(b * NN + i_lo)) * NN + q * 128 + 2 * tg;
    const int* pH = mask + ((size_t)(b * NN + i_hi)) * NN + q * 128 + 2 * tg;

    float T0 = 0.f, A0 = 0.f, P0 = 0.f, T1 = 0.f, A1 = 0.f, P1 = 0.f;
    int   C0 = 0, C1 = 0;

    const float L2E  = 1.44269504f;
    const float N5L2 = -7.21347520f;    // -5*log2(e)

    // depth-4 circular mask pipeline + 1-deep B-fragment prefetch
    int2 mL[4], mH[4];
#pragma unroll
    for (int k = 0; k < 4; k++) {
        mL[k] = *reinterpret_cast<const int2*>(pL + k * 8);
        mH[k] = *reinterpret_cast<const int2*>(pH + k * 8);
    }
    unsigned bf[4];
    ldsm4(bf, sB_u32 + (unsigned)(q * 128 + (lane & 7)) * RSTRIDE
               + (unsigned)((lane >> 3) << 4));

#pragma unroll 2
    for (int t = 0; t < 16; t++) {
        // B fragment for next tile (smem, short latency)
        unsigned bfN[4];
        {
            const int tn = (t < 15) ? t + 1 : 15;
            unsigned an = sB_u32 + (unsigned)(q * 128 + tn * 8 + (lane & 7)) * RSTRIDE
                        + (unsigned)((lane >> 3) << 4);
            ldsm4(bfN, an);
        }

        // Gram for this 16x8 tile
        float d[4];
        const float z[4] = {0.f, 0.f, 0.f, 0.f};
        mma_bf16(d, aLo, &bf[0], z);
        mma_bf16(d, aHi, &bf[2], d);

        // consume mask slot t&3, then refill it with tile t+4 (DRAM hidden)
        int2 cL = mL[t & 3], cH = mH[t & 3];
        if (t < 12) {
            mL[t & 3] = *reinterpret_cast<const int2*>(pL + (t + 4) * 8);
            mH[t & 3] = *reinterpret_cast<const int2*>(pH + (t + 4) * 8);
        }

        const int j0 = q * 128 + t * 8;
        float2 njp = *reinterpret_cast<const float2*>(sN + j0 + 2 * tg);

        // 4 elements: (d0,d1) row i_lo cols j0+2tg,+1 ; (d2,d3) row i_hi
        float ninj[4] = {ni_lo + njp.x, ni_lo + njp.y, ni_hi + njp.x, ni_hi + njp.y};
        int   mi[4]   = {cL.x, cL.y, cH.x, cH.y};
#pragma unroll
        for (int c = 0; c < 4; c++) {
            float ssq  = fmaxf(fmaf(-2.f, d[c], ninj[c]), 0.f);
            float dist = ssq * rsqrtf(fmaxf(ssq, 1e-37f));        // MUFU
            float u    = exp2f(fmaf(dist, L2E, N5L2));            // MUFU
            float sim  = __fdividef(1.f, 1.f + u);                // MUFU
            // e^sim via degree-5 Taylor (sim in (0,1))
            float e = fmaf(sim, 8.3333333e-3f, 4.1666667e-2f);
            e = fmaf(sim, e, 0.16666667f);
            e = fmaf(sim, e, 0.5f);
            e = fmaf(sim, e, 1.f);
            e = fmaf(sim, e, 1.f);
            float mf = (float)mi[c];
            if (c < 2) { T0 += e; A0 = fmaf(mf, e, A0); P0 = fmaf(mf, sim, P0); C0 += mi[c]; }
            else       { T1 += e; A1 = fmaf(mf, e, A1); P1 = fmaf(mf, sim, P1); C1 += mi[c]; }
        }

        bf[0] = bfN[0]; bf[1] = bfN[1]; bf[2] = bfN[2]; bf[3] = bfN[3];
    }

    // reduce across the 4 lanes (tg) sharing each row
    float c0f = (float)C0, c1f = (float)C1;
#pragma unroll
    for (int o = 2; o > 0; o >>= 1) {
        T0 += __shfl_down_sync(0xffffffffu, T0, o, 4);
        A0 += __shfl_down_sync(0xffffffffu, A0, o, 4);
        P0 += __shfl_down_sync(0xffffffffu, P0, o, 4);
        c0f += __shfl_down_sync(0xffffffffu, c0f, o, 4);
        T1 += __shfl_down_sync(0xffffffffu, T1, o, 4);
        A1 += __shfl_down_sync(0xffffffffu, A1, o, 4);
        P1 += __shfl_down_sync(0xffffffffu, P1, o, 4);
        c1f += __shfl_down_sync(0xffffffffu, c1f, o, 4);
    }
    if (tg == 0) {
        sRow[(size_t)(rg * 16 + g) * 8 + q]     = make_float4(T0, A0, P0, c0f);
        sRow[(size_t)(rg * 16 + g + 8) * 8 + q] = make_float4(T1, A1, P1, c1f);
    }
    __syncthreads();

    // ---------------- Phase C: per-row closed form (warp 0) -----------------
    if (tid < 32) {
        const int row = tid;
        const int i   = i0 + row;
        float4 s = make_float4(0.f, 0.f, 0.f, 0.f);
#pragma unroll
        for (int qq = 0; qq < 8; qq++) {
            float4 v = sRow[(size_t)row * 8 + qq];
            s.x += v.x; s.y += v.y; s.z += v.z; s.w += v.w;
        }
        const float EXDIAG_T = 2.69860f;    // Taylor-5 of e^{sigmoid(5)}
        float md = (mask[((size_t)(b * NN + i)) * NN + i] != 0) ? 1.f : 0.f;
        float S  = s.x - s.y - (1.f - md) * EXDIAG_T;
        float L  = __logf(S);
        float contrib = s.w * L - s.z + s.y * __fdividef(1.f, S);
#pragma unroll
        for (int o = 16; o > 0; o >>= 1)
            contrib += __shfl_down_sync(0xffffffffu, contrib, o);
        if (tid == 0) {
            g_part[b * 32 + blockIdx.x] = contrib;
            __threadfence();
            unsigned v = atomicAdd(&g_done, 1u);
            sIsLast = (v == 127u);
        }
    }
    __syncthreads();

    // Last CTA: deterministic fixed-order tree over the 128 partials
    if (sIsLast) {
        double* dsh = reinterpret_cast<double*>(smem);
        if (tid < 128) dsh[tid] = (double)g_part[tid];
        __syncthreads();
#pragma unroll
        for (int s = 64; s > 0; s >>= 1) {
            if (tid < s) dsh[tid] += dsh[tid + s];
            __syncthreads();
        }
        if (tid == 0) {
            out[0] = (float)dsh[0];
            g_done = 0;                 // reset for next replay
        }
    }
}

// ---------------------------------------------------------------------------
extern "C" void kernel_launch(void* const* d_in, const int* in_sizes, int n_in,
                              void* d_out, int out_size) {
    (void)in_sizes; (void)n_in; (void)out_size;
    const float* emb    = (const float*)d_in[0];   // [4,1024,32]
    const float* coords = (const float*)d_in[1];   // [4,1024,2]
    const int*   mask   = (const int*)d_in[2];     // [4,1024,1024] bool->int32
    float* out          = (float*)d_out;           // scalar

    size_t smem = (size_t)NN * RSTRIDE              // sB    81920
                + (size_t)NN * sizeof(float)        // sN     4096
                + (size_t)32 * 8 * sizeof(float4);  // sRow   4096
    cudaFuncSetAttribute(fused_kernel, cudaFuncAttributeMaxDynamicSharedMemorySize,
                         (int)smem);
    fused_kernel<<<dim3(32, 4), 512, smem>>>(emb, coords, mask, out);
}